// round 13
// baseline (speedup 1.0000x reference)
#include <cuda_runtime.h>
#include <cuda_fp16.h>
#include <cstdint>
#include <math.h>

#define SEQ   8
#define FEAT  2048
#define DOUT  1152
#define TLEN  28
#define WAY   5
#define SHOT  5
#define NQv   500
#define NSv   25
#define RQ    (NQv*SEQ)     /* 4000 query frame rows   */
#define RS    (NSv*SEQ)     /* 200 support frame rows  */
#define RALL  (RQ+RS)       /* 4200                    */
#define MQ    (NQv*TLEN)    /* 14000 query tuples      */
#define MS    (NSv*TLEN)    /* 700 support tuples      */

// padded dims (multiples of 128 for the tensor GEMM; no bounds checks needed)
#define MTP   4224          /* padded frame rows                  */
#define NTP   4608          /* 4 planes x 1152 output cols        */
#define MQP   14080         /* padded query tuples                */
#define MSP   768           /* padded support tuples              */

// ---------------- scratch (static device memory; no allocations) -------------
__device__ float   d_PE [SEQ*FEAT];          // positional encoding table
__device__ __half  d_X  [MTP*FEAT];
__device__ __half  d_Wt [NTP*FEAT];
__device__ __half  d_P  [(size_t)MTP*NTP];   // 4-plane frame projections (fp16)
__device__ __half  d_QK [(size_t)MQP*DOUT];
__device__ __half  d_QV [(size_t)MQP*DOUT];
__device__ __half  d_SK [(size_t)MSP*DOUT];
__device__ __half  d_SV [(size_t)MSP*DOUT];
__device__ float   d_SVf[(size_t)MSP*DOUT];
__device__ float   d_S  [(size_t)MQP*MSP];
__device__ float   d_Wm [(size_t)MQP*MSP];
__device__ float   d_qn [MQ];
__device__ float   d_Gp [20*140*140];        // per-(class,kseg) Gram partials
__device__ float   d_G  [WAY*140*140];

__constant__ int c_tup[TLEN*2] = {
  0,1, 0,2, 0,3, 0,4, 0,5, 0,6, 0,7,
  1,2, 1,3, 1,4, 1,5, 1,6, 1,7,
  2,3, 2,4, 2,5, 2,6, 2,7,
  3,4, 3,5, 3,6, 3,7,
  4,5, 4,6, 4,7,
  5,6, 5,7,
  6,7
};

// ======================= generic-target helpers ==============================
__device__ __forceinline__ uint32_t smem_u32(const void* p) {
  uint32_t a;
  asm("{ .reg .u64 t; cvta.to.shared.u64 t, %1; cvt.u32.u64 %0, t; }" : "=r"(a) : "l"(p));
  return a;
}
__device__ __forceinline__ void ldsm4(uint32_t& r0, uint32_t& r1, uint32_t& r2,
                                      uint32_t& r3, uint32_t a) {
  asm volatile("ldmatrix.sync.aligned.m8n8.x4.shared.b16 {%0,%1,%2,%3}, [%4];"
               : "=r"(r0), "=r"(r1), "=r"(r2), "=r"(r3) : "r"(a));
}
__device__ __forceinline__ void mma_f16(float* c, const uint32_t* a, const uint32_t* b) {
  asm volatile("mma.sync.aligned.m16n8k16.row.col.f32.f16.f16.f32 "
               "{%0,%1,%2,%3}, {%4,%5,%6,%7}, {%8,%9}, {%0,%1,%2,%3};"
               : "+f"(c[0]), "+f"(c[1]), "+f"(c[2]), "+f"(c[3])
               : "r"(a[0]), "r"(a[1]), "r"(a[2]), "r"(a[3]), "r"(b[0]), "r"(b[1]));
}
__device__ __forceinline__ float warpReduceSum(float v) {
  #pragma unroll
  for (int o = 16; o; o >>= 1) v += __shfl_xor_sync(0xffffffffu, v, o);
  return v;
}
__device__ __forceinline__ float warpReduceMax(float v) {
  #pragma unroll
  for (int o = 16; o; o >>= 1) v = fmaxf(v, __shfl_xor_sync(0xffffffffu, v, o));
  return v;
}

// ======================= fp16 HMMA GEMM (single product) =====================
#define STAGES  3
#define TILE_B  16384                 /* 128 rows x 64 fp16 (128B rows) */
#define STAGE_B (2*TILE_B)            /* A tile + B tile = 32KB */
#define GSMEM   (STAGES*STAGE_B)      /* 96 KB -> 2 CTAs/SM */

__device__ __forceinline__ void load_stage(
    const __half* __restrict__ A, const __half* __restrict__ B,
    uint32_t stage, int m0, int n0, int k0, int K, int tid)
{
  #pragma unroll
  for (int i = 0; i < 8; i++) {
    int id   = tid + i * 256;
    int tile = id >> 10;                      // 0:A 1:B
    int row  = (id >> 3) & 127;
    int c16  = id & 7;                        // 16B chunk within 128B row
    const __half* base = (tile == 0) ? A : B;
    int r = ((tile == 0) ? m0 : n0) + row;
    const __half* src = base + (size_t)r * K + k0 + c16 * 8;
    uint32_t dst = stage + tile * TILE_B + (row << 7) + ((c16 ^ (row & 7)) << 4);
    asm volatile("cp.async.cg.shared.global [%0], [%1], 16;" :: "r"(dst), "l"(src) : "memory");
  }
  asm volatile("cp.async.commit_group;" ::: "memory");
}

template<int HALF_OUT>
__device__ __forceinline__ void gemm_core(
    const __half* __restrict__ A, const __half* __restrict__ B,
    void* __restrict__ C, int K, int ldc, int m0, int n0, char* smem)
{
  const uint32_t sb = smem_u32(smem);
  const int tid  = threadIdx.x;
  const int lane = tid & 31;
  const int wid  = tid >> 5;
  const int wm   = wid & 1;           // 2 m-blocks of 64
  const int wn   = wid >> 1;          // 4 n-blocks of 32
  const int NC = K >> 6;

  const int q     = lane >> 3;
  const int lrow  = (q & 1) * 8 + (lane & 7);
  const int khalf = q >> 1;

  // smem reuse guard for persistent callers (all warps past previous tile)
  __syncthreads();

  float acc[4][4][4];
  #pragma unroll
  for (int a = 0; a < 4; a++)
    #pragma unroll
    for (int b = 0; b < 4; b++)
      #pragma unroll
      for (int d = 0; d < 4; d++) acc[a][b][d] = 0.f;

  load_stage(A, B, sb + 0 * STAGE_B, m0, n0, 0,  K, tid);
  load_stage(A, B, sb + 1 * STAGE_B, m0, n0, 64, K, tid);

  for (int c = 0; c < NC; c++) {
    asm volatile("cp.async.wait_group 1;" ::: "memory");
    __syncthreads();
    if (c + 2 < NC)
      load_stage(A, B, sb + ((c + 2) % STAGES) * STAGE_B,
                 m0, n0, (c + 2) * 64, K, tid);
    else
      asm volatile("cp.async.commit_group;" ::: "memory");   // keep group count uniform

    const uint32_t st = sb + (c % STAGES) * STAGE_B;
    #pragma unroll
    for (int ks = 0; ks < 4; ks++) {
      const int cc = 2 * ks + khalf;
      uint32_t af[4][4];
      #pragma unroll
      for (int mi = 0; mi < 4; mi++) {
        int r = wm * 64 + mi * 16 + lrow;
        uint32_t ad = st + (r << 7) + ((cc ^ (r & 7)) << 4);
        ldsm4(af[mi][0], af[mi][1], af[mi][2], af[mi][3], ad);
      }
      uint32_t bf[4][2];
      #pragma unroll
      for (int g = 0; g < 2; g++) {
        int r = wn * 32 + g * 16 + lrow;
        uint32_t bd = st + TILE_B + (r << 7) + ((cc ^ (r & 7)) << 4);
        uint32_t t0, t1, t2, t3;
        ldsm4(t0, t1, t2, t3, bd);
        bf[2*g][0] = t0; bf[2*g][1] = t2; bf[2*g+1][0] = t1; bf[2*g+1][1] = t3;
      }
      #pragma unroll
      for (int mi = 0; mi < 4; mi++)
        #pragma unroll
        for (int nj = 0; nj < 4; nj++)
          mma_f16(acc[mi][nj], af[mi], bf[nj]);
    }
  }

  #pragma unroll
  for (int mi = 0; mi < 4; mi++) {
    int r = m0 + wm * 64 + mi * 16 + (lane >> 2);
    #pragma unroll
    for (int nj = 0; nj < 4; nj++) {
      int col = n0 + wn * 32 + nj * 8 + ((lane & 3) << 1);
      if (HALF_OUT) {
        __half* Ch = (__half*)C;
        *(__half2*)&Ch[(size_t)r * ldc + col] =
            __floats2half2_rn(acc[mi][nj][0], acc[mi][nj][1]);
        *(__half2*)&Ch[(size_t)(r + 8) * ldc + col] =
            __floats2half2_rn(acc[mi][nj][2], acc[mi][nj][3]);
      } else {
        float* Cf = (float*)C;
        *(float2*)&Cf[(size_t)r * ldc + col]       = make_float2(acc[mi][nj][0], acc[mi][nj][1]);
        *(float2*)&Cf[(size_t)(r + 8) * ldc + col] = make_float2(acc[mi][nj][2], acc[mi][nj][3]);
      }
    }
  }
}

// projection GEMM: fp16 output
__global__ void __launch_bounds__(256, 2)
gemm_f16(const __half* __restrict__ A, const __half* __restrict__ B,
         __half* __restrict__ C, int K, int ldc)
{
  extern __shared__ char smem[];
  gemm_core<1>(A, B, C, K, ldc, blockIdx.x * 128, blockIdx.y * 128, smem);
}

// persistent merged score GEMMs: tile z=0 -> QK*SK^T -> S ; z=1 -> QV*SV^T -> Wm
#define SC_MT (MQP/128)     /* 110 */
#define SC_NT (MSP/128)     /* 6   */
#define SC_TILES (SC_MT*SC_NT*2)
__global__ void __launch_bounds__(256, 2)
gemm_scores(const __half* __restrict__ QK, const __half* __restrict__ SK,
            float* __restrict__ S,
            const __half* __restrict__ QV, const __half* __restrict__ SV,
            float* __restrict__ Wm, int K, int ldc)
{
  extern __shared__ char smem[];
  for (int tile = blockIdx.x; tile < SC_TILES; tile += gridDim.x) {
    int z  = tile / (SC_MT * SC_NT);
    int t2 = tile % (SC_MT * SC_NT);
    int mi = t2 % SC_MT;                // m-major: concurrent blocks share B panel
    int ni = t2 / SC_MT;
    const __half* A = z ? QV : QK;
    const __half* B = z ? SV : SK;
    float* C        = z ? Wm : S;
    gemm_core<0>(A, B, C, K, ldc, mi * 128, ni * 128, smem);
  }
}

// ---------------- kernel 0: PE table + weight transpose (fused) --------------
// z 0..3 -> transpose plane z ; z==4 -> build PE table
__global__ void pre_w(const float* __restrict__ kw, const float* __restrict__ vw) {
  if (blockIdx.z < 4) {
    __shared__ float tile[32][33];
    int p = blockIdx.z;
    const float* w = (p < 2) ? kw : vw;
    int k0 = blockIdx.x * 32, c0 = blockIdx.y * 32;
    int rbase = (p & 1) * FEAT;
    int tx = threadIdx.x, ty = threadIdx.y;  // 32 x 8
    #pragma unroll
    for (int i = 0; i < 32; i += 8)
      tile[ty + i][tx] = w[(size_t)(rbase + k0 + ty + i) * DOUT + c0 + tx];
    __syncthreads();
    #pragma unroll
    for (int i = 0; i < 32; i += 8) {
      size_t o = (size_t)(p * DOUT + c0 + ty + i) * FEAT + k0 + tx;
      d_Wt[o] = __float2half(tile[tx][ty + i]);
    }
  } else {
    int bid = blockIdx.y * gridDim.x + blockIdx.x;
    int t = bid * 256 + threadIdx.y * 32 + threadIdx.x;
    if (t < SEQ * FEAT) {
      int d  = t & (FEAT - 1);
      int fr = t >> 11;
      float freq = expf((float)(d & ~1) * (-9.210340371976184f / 2048.0f));
      float ang  = (float)fr * freq;
      d_PE[t] = (d & 1) ? cosf(ang) : sinf(ang);
    }
  }
}

// ---------------- kernel 1: frames + PE -> fp16, vectorized x8 ---------------
__global__ void prep(const float* __restrict__ q, const float* __restrict__ s) {
  int i8 = (blockIdx.x * 256 + threadIdx.x) * 8;
  if (i8 >= MTP * FEAT) return;
  int r = i8 >> 11;
  __half h[8];
  if (r >= RALL) {
    #pragma unroll
    for (int i = 0; i < 8; i++) h[i] = __float2half(0.f);
  } else {
    const float* src = (r < RQ) ? (q + i8) : (s + (i8 - RQ * FEAT));
    float4 a = *(const float4*)src;
    float4 b = *(const float4*)(src + 4);
    const float* pe = d_PE + (i8 & (SEQ * FEAT - 1));
    float4 p0 = *(const float4*)pe;
    float4 p1 = *(const float4*)(pe + 4);
    h[0] = __float2half(a.x + p0.x); h[1] = __float2half(a.y + p0.y);
    h[2] = __float2half(a.z + p0.z); h[3] = __float2half(a.w + p0.w);
    h[4] = __float2half(b.x + p1.x); h[5] = __float2half(b.y + p1.y);
    h[6] = __float2half(b.z + p1.z); h[7] = __float2half(b.w + p1.w);
  }
  *(uint4*)&d_X[i8] = *(const uint4*)h;
}

// ---------------- Gram: K-split partials (fp32) + reduce ---------------------
#define BM 64
#define BN 64
#define BK 16
#define KSEG 288
__global__ void __launch_bounds__(256)
gram_part(const float* __restrict__ Abase) {
  const int z = blockIdx.z;                // 0..19 = class*4 + kseg
  const int cls = z >> 2, seg = z & 3;
  const float* A = Abase + (size_t)cls * 140 * DOUT + seg * KSEG;
  const float* B = A;
  float* C = d_Gp + (size_t)z * 19600;
  __shared__ __align__(16) float As[BK][BM + 4];
  __shared__ __align__(16) float Bs[BK][BN + 4];
  int tid = threadIdx.x;
  int tx = tid & 15, ty = tid >> 4;
  int m0 = blockIdx.x * BM, n0 = blockIdx.y * BN;
  int lr = tid >> 2;
  int lc = (tid & 3) << 2;
  float acc[4][4] = {};
  const float* Aptr = A + (size_t)(m0 + lr) * DOUT + lc;
  const float* Bptr = B + (size_t)(n0 + lr) * DOUT + lc;
  bool am = (m0 + lr) < 140;
  bool bn = (n0 + lr) < 140;
  for (int k0 = 0; k0 < KSEG; k0 += BK) {
    float4 av = am ? *(const float4*)(Aptr + k0) : make_float4(0, 0, 0, 0);
    float4 bv = bn ? *(const float4*)(Bptr + k0) : make_float4(0, 0, 0, 0);
    As[lc + 0][lr] = av.x; As[lc + 1][lr] = av.y;
    As[lc + 2][lr] = av.z; As[lc + 3][lr] = av.w;
    Bs[lc + 0][lr] = bv.x; Bs[lc + 1][lr] = bv.y;
    Bs[lc + 2][lr] = bv.z; Bs[lc + 3][lr] = bv.w;
    __syncthreads();
    #pragma unroll
    for (int k = 0; k < BK; k++) {
      float4 a4 = *(const float4*)&As[k][ty << 2];
      float4 b4 = *(const float4*)&Bs[k][tx << 2];
      float ar[4] = {a4.x, a4.y, a4.z, a4.w};
      float br[4] = {b4.x, b4.y, b4.z, b4.w};
      #pragma unroll
      for (int i = 0; i < 4; i++)
        #pragma unroll
        for (int j = 0; j < 4; j++)
          acc[i][j] += ar[i] * br[j];
    }
    __syncthreads();
  }
  #pragma unroll
  for (int i = 0; i < 4; i++) {
    int m = m0 + (ty << 2) + i;
    if (m >= 140) continue;
    #pragma unroll
    for (int j = 0; j < 4; j++) {
      int n = n0 + (tx << 2) + j;
      if (n < 140) C[(size_t)m * 140 + n] = acc[i][j];
    }
  }
}
__global__ void gram_reduce() {
  int i = (blockIdx.x * 256 + threadIdx.x) * 4;
  if (i >= WAY * 19600) return;
  int cls = i / 19600, off = i % 19600;
  const float* base = d_Gp + (size_t)cls * 4 * 19600 + off;
  float4 s0 = *(const float4*)(base);
  float4 s1 = *(const float4*)(base + 19600);
  float4 s2 = *(const float4*)(base + 2 * 19600);
  float4 s3 = *(const float4*)(base + 3 * 19600);
  float4 r;
  r.x = (s0.x + s1.x) + (s2.x + s3.x);
  r.y = (s0.y + s1.y) + (s2.y + s3.y);
  r.z = (s0.z + s1.z) + (s2.z + s3.z);
  r.w = (s0.w + s1.w) + (s2.w + s3.w);
  *(float4*)&d_G[i] = r;
}

// ---------------- kernel: per-item combine (two-pass, low registers) ---------
#define CSMEM (8*NTP*2)
__global__ void __launch_bounds__(256, 2)
combine2(const float* __restrict__ kb, const float* __restrict__ vb,
         const float* __restrict__ gamma, const float* __restrict__ beta) {
  extern __shared__ __half sPh[];   // 8 * 4608 halves
  const int item = blockIdx.x;
  const bool isQ = item < NQv;
  const int tid = threadIdx.x;
  const int lane = tid & 31;
  const int w = tid >> 5;
  const __half* src = d_P + (size_t)item * SEQ * NTP;
  for (int i = tid * 8; i < SEQ * NTP; i += 256 * 8)
    *(uint4*)&sPh[i] = *(const uint4*)&src[i];
  __syncthreads();
  const int mBase = isQ ? item * TLEN : (item - NQv) * TLEN;
  for (int t = w; t < TLEN; t += 8) {
    const int fi = c_tup[2 * t], fj = c_tup[2 * t + 1];
    const __half* pA = sPh + fi * NTP;
    const __half* pB = sPh + fj * NTP;
    const size_t mOff = (size_t)(mBase + t) * DOUT;
    // ---- pass A: LN stats for K + V outputs + ||v||^2 (no x storage) ----
    float s1 = 0.f, s2 = 0.f, qacc = 0.f;
    #pragma unroll 4
    for (int i = 0; i < 36; i++) {
      int d = lane + i * 32;
      float x = __half2float(pA[d]) + __half2float(pB[DOUT + d]) + kb[d];
      s1 += x; s2 += x * x;
      float y = __half2float(pA[2 * DOUT + d]) + __half2float(pB[3 * DOUT + d]) + vb[d];
      if (isQ) { d_QV[mOff + d] = __float2half(y); }
      else     { d_SV[mOff + d] = __float2half(y); d_SVf[mOff + d] = y; }
      qacc += y * y;
    }
    s1 = warpReduceSum(s1);
    s2 = warpReduceSum(s2);
    if (isQ) {
      qacc = warpReduceSum(qacc);
      if (lane == 0) d_qn[mBase + t] = qacc;
    }
    float mu  = s1 * (1.0f / DOUT);
    float var = s2 * (1.0f / DOUT) - mu * mu;
    float inv = rsqrtf(var + 1e-5f);
    // ---- pass B: recompute x from smem, apply LN, write K ----
    #pragma unroll 4
    for (int i = 0; i < 36; i++) {
      int d = lane + i * 32;
      float x = __half2float(pA[d]) + __half2float(pB[DOUT + d]) + kb[d];
      float z = (x - mu) * inv * gamma[d] + beta[d];
      if (isQ) d_QK[mOff + d] = __float2half(z);
      else     d_SK[mOff + d] = __float2half(z);
    }
  }
}

// ---------------- finalize: softmax + Gram quadratic form + logits -----------
#define QPB 4
#define FSMEM ((19600 + QPB*TLEN*140 + 8) * 4)
__global__ void __launch_bounds__(256)
finalize_k(const float* __restrict__ gt, const float* __restrict__ tw,
           float* __restrict__ out) {
  extern __shared__ float sm[];
  float* Gs  = sm;                  // 19600
  float* es  = sm + 19600;          // QPB * 28 * 140
  float* red = es + QPB * TLEN * 140;  // 8
  const int qb = blockIdx.x, c = blockIdx.y;
  const int tid = threadIdx.x;
  const int lane = tid & 31;
  const int w = tid >> 5;
  const float* Gsrc = d_G + (size_t)c * 19600;
  for (int idx = tid * 4; idx < 19600; idx += 256 * 4)
    *(float4*)&Gs[idx] = *(const float4*)&Gsrc[idx];
  __syncthreads();

  const float gscale = gt[0] * tw[0];
  #pragma unroll
  for (int qi = 0; qi < QPB; qi++) {
    const int qq = qb * QPB + qi;
    float* e_q = es + qi * TLEN * 140;
    float dist = 0.f;
    if (w < 7) {
      const float scale = rsqrtf((float)DOUT);
      const int t0 = w * 4;
      float Zs[4], TWs[4];
      #pragma unroll
      for (int tt = 0; tt < 4; tt++) {
        const int m = qq * TLEN + t0 + tt;
        const float* Srow = d_S  + (size_t)m * MSP + c * 140;
        const float* Wrow = d_Wm + (size_t)m * MSP + c * 140;
        float ev[5];
        float lmax = -INFINITY;
        #pragma unroll
        for (int i = 0; i < 5; i++) {
          int j = lane + i * 32;
          if (j < 140) { ev[i] = Srow[j] * scale; lmax = fmaxf(lmax, ev[i]); }
          else ev[i] = -INFINITY;
        }
        lmax = warpReduceMax(lmax);
        float lsum = 0.f, lw = 0.f;
        #pragma unroll
        for (int i = 0; i < 5; i++) {
          int j = lane + i * 32;
          if (j < 140) {
            float e = __expf(ev[i] - lmax);
            e_q[(t0 + tt) * 140 + j] = e;
            lsum += e;
            lw   += e * Wrow[j];
          }
        }
        Zs[tt]  = warpReduceSum(lsum);
        TWs[tt] = warpReduceSum(lw);
      }
      __syncwarp();
      float hq[5][4];
      #pragma unroll
      for (int i = 0; i < 5; i++)
        #pragma unroll
        for (int tt = 0; tt < 4; tt++) hq[i][tt] = 0.f;
      for (int j = 0; j < 140; j++) {
        float e4[4];
        #pragma unroll
        for (int tt = 0; tt < 4; tt++) e4[tt] = e_q[(t0 + tt) * 140 + j];
        const float* Grow = Gs + j * 140;
        #pragma unroll
        for (int i = 0; i < 5; i++) {
          int jc = lane + i * 32;
          float g = (jc < 140) ? Grow[jc] : 0.f;
          #pragma unroll
          for (int tt = 0; tt < 4; tt++) hq[i][tt] += g * e4[tt];
        }
      }
      #pragma unroll
      for (int tt = 0; tt < 4; tt++) {
        float qp = 0.f;
        #pragma unroll
        for (int i = 0; i < 5; i++) {
          int jc = lane + i * 32;
          if (jc < 140) qp += hq[i][tt] * e_q[(t0 + tt) * 140 + jc];
        }
        qp = warpReduceSum(qp);
        float invZ = 1.0f / Zs[tt];
        dist += d_qn[qq * TLEN + t0 + tt] - 2.f * TWs[tt] * invZ + qp * invZ * invZ;
      }
    }
    if (lane == 0) red[w] = dist;
    __syncthreads();
    if (tid == 0) {
      float s = 0.f;
      #pragma unroll
      for (int i = 0; i < 7; i++) s += red[i];
      out[qq * WAY + c] = -(s * (1.0f / TLEN)) * gscale;
    }
    __syncthreads();     // red reuse guard for next query
  }
}

// ---------------- launcher ---------------------------------------------------
extern "C" void kernel_launch(void* const* d_in, const int* in_sizes, int n_in,
                              void* d_out, int out_size) {
  const float* support = (const float*)d_in[0];
  /* d_in[1] = support_labels: sorted & balanced; reference uses a reshape */
  const float* queries = (const float*)d_in[2];
  const float* kw    = (const float*)d_in[3];
  const float* kb    = (const float*)d_in[4];
  const float* vw    = (const float*)d_in[5];
  const float* vb    = (const float*)d_in[6];
  const float* gamma = (const float*)d_in[7];
  const float* beta  = (const float*)d_in[8];
  const float* gt    = (const float*)d_in[9];
  const float* tw    = (const float*)d_in[10];
  float* out = (float*)d_out;

  __half *X, *Wt, *P, *QK, *QV, *SK, *SV;
  float *SVf, *S, *Wm;
  cudaGetSymbolAddress((void**)&X,   d_X);
  cudaGetSymbolAddress((void**)&Wt,  d_Wt);
  cudaGetSymbolAddress((void**)&P,   d_P);
  cudaGetSymbolAddress((void**)&QK,  d_QK);
  cudaGetSymbolAddress((void**)&QV,  d_QV);
  cudaGetSymbolAddress((void**)&SK,  d_SK);
  cudaGetSymbolAddress((void**)&SV,  d_SV);
  cudaGetSymbolAddress((void**)&SVf, d_SVf);
  cudaGetSymbolAddress((void**)&S,   d_S);
  cudaGetSymbolAddress((void**)&Wm,  d_Wm);

  cudaFuncSetAttribute(gemm_f16,    cudaFuncAttributeMaxDynamicSharedMemorySize, GSMEM);
  cudaFuncSetAttribute(gemm_scores, cudaFuncAttributeMaxDynamicSharedMemorySize, GSMEM);
  cudaFuncSetAttribute(combine2,    cudaFuncAttributeMaxDynamicSharedMemorySize, CSMEM);
  cudaFuncSetAttribute(finalize_k,  cudaFuncAttributeMaxDynamicSharedMemorySize, FSMEM);

  // launch 0: fused PE table + weight transpose
  pre_w<<<dim3(FEAT / 32, DOUT / 32, 5), dim3(32, 8)>>>(kw, vw);
  // launch 1: frames + PE -> fp16 (vectorized x8)
  prep<<<(MTP * FEAT / 8 + 255) / 256, 256>>>(queries, support);
  // launch 2: all 4 projection planes, fp16 output
  gemm_f16<<<dim3(MTP / 128, NTP / 128), 256, GSMEM>>>(X, Wt, P, FEAT, NTP);
  // launch 3 (ncu-captured): per-item tuple combine + LN + fp16 casts
  combine2<<<NQv + NSv, 256, CSMEM>>>(kb, vb, gamma, beta);
  // per-class value Gram partials (K-split x4) + reduce
  gram_part<<<dim3(3, 3, 20), 256>>>(SVf);
  gram_reduce<<<(WAY * 19600 / 4 + 255) / 256, 256>>>();
  // persistent merged scores + value-overlap GEMMs
  gemm_scores<<<296, 256, GSMEM>>>(QK, SK, S, QV, SV, Wm, DOUT, MSP);
  // softmax + quadratic-form distance + logits (4 queries per block)
  finalize_k<<<dim3(NQv / QPB, WAY), 256, FSMEM>>>(gt, tw, out);
}

// round 14
// speedup vs baseline: 1.2270x; 1.2270x over previous
#include <cuda_runtime.h>
#include <cuda_fp16.h>
#include <cstdint>
#include <math.h>

#define SEQ   8
#define FEAT  2048
#define DOUT  1152
#define TLEN  28
#define WAY   5
#define SHOT  5
#define NQv   500
#define NSv   25
#define RQ    (NQv*SEQ)     /* 4000 query frame rows   */
#define RS    (NSv*SEQ)     /* 200 support frame rows  */
#define RALL  (RQ+RS)       /* 4200                    */
#define MQ    (NQv*TLEN)    /* 14000 query tuples      */
#define MS    (NSv*TLEN)    /* 700 support tuples      */

// padded dims (multiples of 128 for the tensor GEMM; no bounds checks needed)
#define MTP   4224          /* padded frame rows                  */
#define NTP   4608          /* 4 planes x 1152 output cols        */
#define MQP   14080         /* padded query tuples                */
#define MSP   768           /* padded support tuples              */

// ---------------- scratch (static device memory; no allocations) -------------
__device__ float   d_PE [SEQ*FEAT];          // positional encoding table
__device__ __half  d_X  [MTP*FEAT];
__device__ __half  d_Wt [NTP*FEAT];
__device__ __half  d_P  [(size_t)MTP*NTP];   // 4-plane frame projections (fp16)
__device__ __half  d_QK [(size_t)MQP*DOUT];
__device__ __half  d_QV [(size_t)MQP*DOUT];
__device__ __half  d_SK [(size_t)MSP*DOUT];
__device__ __half  d_SV [(size_t)MSP*DOUT];
__device__ float   d_SVf[(size_t)MSP*DOUT];
__device__ float   d_S  [(size_t)MQP*MSP];
__device__ float   d_Wm [(size_t)MQP*MSP];
__device__ float   d_qn [MQ];
__device__ float   d_Gp [20*140*140];        // per-(class,kseg) Gram partials
__device__ float   d_G  [WAY*140*140];

__constant__ int c_tup[TLEN*2] = {
  0,1, 0,2, 0,3, 0,4, 0,5, 0,6, 0,7,
  1,2, 1,3, 1,4, 1,5, 1,6, 1,7,
  2,3, 2,4, 2,5, 2,6, 2,7,
  3,4, 3,5, 3,6, 3,7,
  4,5, 4,6, 4,7,
  5,6, 5,7,
  6,7
};

// ======================= generic-target helpers ==============================
__device__ __forceinline__ uint32_t smem_u32(const void* p) {
  uint32_t a;
  asm("{ .reg .u64 t; cvta.to.shared.u64 t, %1; cvt.u32.u64 %0, t; }" : "=r"(a) : "l"(p));
  return a;
}
__device__ __forceinline__ void ldsm4(uint32_t& r0, uint32_t& r1, uint32_t& r2,
                                      uint32_t& r3, uint32_t a) {
  asm volatile("ldmatrix.sync.aligned.m8n8.x4.shared.b16 {%0,%1,%2,%3}, [%4];"
               : "=r"(r0), "=r"(r1), "=r"(r2), "=r"(r3) : "r"(a));
}
__device__ __forceinline__ void mma_f16(float* c, const uint32_t* a, const uint32_t* b) {
  asm volatile("mma.sync.aligned.m16n8k16.row.col.f32.f16.f16.f32 "
               "{%0,%1,%2,%3}, {%4,%5,%6,%7}, {%8,%9}, {%0,%1,%2,%3};"
               : "+f"(c[0]), "+f"(c[1]), "+f"(c[2]), "+f"(c[3])
               : "r"(a[0]), "r"(a[1]), "r"(a[2]), "r"(a[3]), "r"(b[0]), "r"(b[1]));
}
__device__ __forceinline__ float warpReduceSum(float v) {
  #pragma unroll
  for (int o = 16; o; o >>= 1) v += __shfl_xor_sync(0xffffffffu, v, o);
  return v;
}
__device__ __forceinline__ float warpReduceMax(float v) {
  #pragma unroll
  for (int o = 16; o; o >>= 1) v = fmaxf(v, __shfl_xor_sync(0xffffffffu, v, o));
  return v;
}

// ======================= fp16 HMMA GEMM (single product) =====================
#define STAGES  3
#define TILE_B  16384                 /* 128 rows x 64 fp16 (128B rows) */
#define STAGE_B (2*TILE_B)            /* A tile + B tile = 32KB */
#define GSMEM   (STAGES*STAGE_B)      /* 96 KB -> 2 CTAs/SM */

__device__ __forceinline__ void load_stage(
    const __half* __restrict__ A, const __half* __restrict__ B,
    uint32_t stage, int m0, int n0, int k0, int K, int tid)
{
  #pragma unroll
  for (int i = 0; i < 8; i++) {
    int id   = tid + i * 256;
    int tile = id >> 10;                      // 0:A 1:B
    int row  = (id >> 3) & 127;
    int c16  = id & 7;                        // 16B chunk within 128B row
    const __half* base = (tile == 0) ? A : B;
    int r = ((tile == 0) ? m0 : n0) + row;
    const __half* src = base + (size_t)r * K + k0 + c16 * 8;
    uint32_t dst = stage + tile * TILE_B + (row << 7) + ((c16 ^ (row & 7)) << 4);
    asm volatile("cp.async.cg.shared.global [%0], [%1], 16;" :: "r"(dst), "l"(src) : "memory");
  }
  asm volatile("cp.async.commit_group;" ::: "memory");
}

template<int HALF_OUT>
__device__ __forceinline__ void gemm_core(
    const __half* __restrict__ A, const __half* __restrict__ B,
    void* __restrict__ C, int K, int ldc, int m0, int n0, char* smem)
{
  const uint32_t sb = smem_u32(smem);
  const int tid  = threadIdx.x;
  const int lane = tid & 31;
  const int wid  = tid >> 5;
  const int wm   = wid & 1;           // 2 m-blocks of 64
  const int wn   = wid >> 1;          // 4 n-blocks of 32
  const int NC = K >> 6;

  const int q     = lane >> 3;
  const int lrow  = (q & 1) * 8 + (lane & 7);
  const int khalf = q >> 1;

  // smem reuse guard for persistent callers (all warps past previous tile)
  __syncthreads();

  float acc[4][4][4];
  #pragma unroll
  for (int a = 0; a < 4; a++)
    #pragma unroll
    for (int b = 0; b < 4; b++)
      #pragma unroll
      for (int d = 0; d < 4; d++) acc[a][b][d] = 0.f;

  load_stage(A, B, sb + 0 * STAGE_B, m0, n0, 0,  K, tid);
  load_stage(A, B, sb + 1 * STAGE_B, m0, n0, 64, K, tid);

  for (int c = 0; c < NC; c++) {
    asm volatile("cp.async.wait_group 1;" ::: "memory");
    __syncthreads();
    if (c + 2 < NC)
      load_stage(A, B, sb + ((c + 2) % STAGES) * STAGE_B,
                 m0, n0, (c + 2) * 64, K, tid);
    else
      asm volatile("cp.async.commit_group;" ::: "memory");   // keep group count uniform

    const uint32_t st = sb + (c % STAGES) * STAGE_B;
    #pragma unroll
    for (int ks = 0; ks < 4; ks++) {
      const int cc = 2 * ks + khalf;
      uint32_t af[4][4];
      #pragma unroll
      for (int mi = 0; mi < 4; mi++) {
        int r = wm * 64 + mi * 16 + lrow;
        uint32_t ad = st + (r << 7) + ((cc ^ (r & 7)) << 4);
        ldsm4(af[mi][0], af[mi][1], af[mi][2], af[mi][3], ad);
      }
      uint32_t bf[4][2];
      #pragma unroll
      for (int g = 0; g < 2; g++) {
        int r = wn * 32 + g * 16 + lrow;
        uint32_t bd = st + TILE_B + (r << 7) + ((cc ^ (r & 7)) << 4);
        uint32_t t0, t1, t2, t3;
        ldsm4(t0, t1, t2, t3, bd);
        bf[2*g][0] = t0; bf[2*g][1] = t2; bf[2*g+1][0] = t1; bf[2*g+1][1] = t3;
      }
      #pragma unroll
      for (int mi = 0; mi < 4; mi++)
        #pragma unroll
        for (int nj = 0; nj < 4; nj++)
          mma_f16(acc[mi][nj], af[mi], bf[nj]);
    }
  }

  #pragma unroll
  for (int mi = 0; mi < 4; mi++) {
    int r = m0 + wm * 64 + mi * 16 + (lane >> 2);
    #pragma unroll
    for (int nj = 0; nj < 4; nj++) {
      int col = n0 + wn * 32 + nj * 8 + ((lane & 3) << 1);
      if (HALF_OUT) {
        __half* Ch = (__half*)C;
        *(__half2*)&Ch[(size_t)r * ldc + col] =
            __floats2half2_rn(acc[mi][nj][0], acc[mi][nj][1]);
        *(__half2*)&Ch[(size_t)(r + 8) * ldc + col] =
            __floats2half2_rn(acc[mi][nj][2], acc[mi][nj][3]);
      } else {
        float* Cf = (float*)C;
        *(float2*)&Cf[(size_t)r * ldc + col]       = make_float2(acc[mi][nj][0], acc[mi][nj][1]);
        *(float2*)&Cf[(size_t)(r + 8) * ldc + col] = make_float2(acc[mi][nj][2], acc[mi][nj][3]);
      }
    }
  }
}

// projection GEMM: fp16 output
__global__ void __launch_bounds__(256, 2)
gemm_f16(const __half* __restrict__ A, const __half* __restrict__ B,
         __half* __restrict__ C, int K, int ldc)
{
  extern __shared__ char smem[];
  gemm_core<1>(A, B, C, K, ldc, blockIdx.x * 128, blockIdx.y * 128, smem);
}

// persistent merged score GEMMs: tile z=0 -> QK*SK^T -> S ; z=1 -> QV*SV^T -> Wm
#define SC_MT (MQP/128)     /* 110 */
#define SC_NT (MSP/128)     /* 6   */
#define SC_TILES (SC_MT*SC_NT*2)
__global__ void __launch_bounds__(256, 2)
gemm_scores(const __half* __restrict__ QK, const __half* __restrict__ SK,
            float* __restrict__ S,
            const __half* __restrict__ QV, const __half* __restrict__ SV,
            float* __restrict__ Wm, int K, int ldc)
{
  extern __shared__ char smem[];
  for (int tile = blockIdx.x; tile < SC_TILES; tile += gridDim.x) {
    int z  = tile / (SC_MT * SC_NT);
    int t2 = tile % (SC_MT * SC_NT);
    int mi = t2 % SC_MT;                // m-major: concurrent blocks share B panel
    int ni = t2 / SC_MT;
    const __half* A = z ? QV : QK;
    const __half* B = z ? SV : SK;
    float* C        = z ? Wm : S;
    gemm_core<0>(A, B, C, K, ldc, mi * 128, ni * 128, smem);
  }
}

// ---------------- kernel 0: PE table + weight transpose (fused) --------------
// z 0..3 -> transpose plane z ; z==4 -> build PE table
__global__ void pre_w(const float* __restrict__ kw, const float* __restrict__ vw) {
  if (blockIdx.z < 4) {
    __shared__ float tile[32][33];
    int p = blockIdx.z;
    const float* w = (p < 2) ? kw : vw;
    int k0 = blockIdx.x * 32, c0 = blockIdx.y * 32;
    int rbase = (p & 1) * FEAT;
    int tx = threadIdx.x, ty = threadIdx.y;  // 32 x 8
    #pragma unroll
    for (int i = 0; i < 32; i += 8)
      tile[ty + i][tx] = w[(size_t)(rbase + k0 + ty + i) * DOUT + c0 + tx];
    __syncthreads();
    #pragma unroll
    for (int i = 0; i < 32; i += 8) {
      size_t o = (size_t)(p * DOUT + c0 + ty + i) * FEAT + k0 + tx;
      d_Wt[o] = __float2half(tile[tx][ty + i]);
    }
  } else {
    int bid = blockIdx.y * gridDim.x + blockIdx.x;
    int t = bid * 256 + threadIdx.y * 32 + threadIdx.x;
    if (t < SEQ * FEAT) {
      int d  = t & (FEAT - 1);
      int fr = t >> 11;
      float freq = expf((float)(d & ~1) * (-9.210340371976184f / 2048.0f));
      float ang  = (float)fr * freq;
      d_PE[t] = (d & 1) ? cosf(ang) : sinf(ang);
    }
  }
}

// ---------------- kernel 1: frames + PE -> fp16, vectorized x8 ---------------
__global__ void prep(const float* __restrict__ q, const float* __restrict__ s) {
  int i8 = (blockIdx.x * 256 + threadIdx.x) * 8;
  if (i8 >= MTP * FEAT) return;
  int r = i8 >> 11;
  __half h[8];
  if (r >= RALL) {
    #pragma unroll
    for (int i = 0; i < 8; i++) h[i] = __float2half(0.f);
  } else {
    const float* src = (r < RQ) ? (q + i8) : (s + (i8 - RQ * FEAT));
    float4 a = *(const float4*)src;
    float4 b = *(const float4*)(src + 4);
    const float* pe = d_PE + (i8 & (SEQ * FEAT - 1));
    float4 p0 = *(const float4*)pe;
    float4 p1 = *(const float4*)(pe + 4);
    h[0] = __float2half(a.x + p0.x); h[1] = __float2half(a.y + p0.y);
    h[2] = __float2half(a.z + p0.z); h[3] = __float2half(a.w + p0.w);
    h[4] = __float2half(b.x + p1.x); h[5] = __float2half(b.y + p1.y);
    h[6] = __float2half(b.z + p1.z); h[7] = __float2half(b.w + p1.w);
  }
  *(uint4*)&d_X[i8] = *(const uint4*)h;
}

// ---------------- Gram: K-split partials (fp32) + reduce ---------------------
#define BM 64
#define BN 64
#define BK 16
#define KSEG 288
__global__ void __launch_bounds__(256)
gram_part(const float* __restrict__ Abase) {
  const int z = blockIdx.z;                // 0..19 = class*4 + kseg
  const int cls = z >> 2, seg = z & 3;
  const float* A = Abase + (size_t)cls * 140 * DOUT + seg * KSEG;
  const float* B = A;
  float* C = d_Gp + (size_t)z * 19600;
  __shared__ __align__(16) float As[BK][BM + 4];
  __shared__ __align__(16) float Bs[BK][BN + 4];
  int tid = threadIdx.x;
  int tx = tid & 15, ty = tid >> 4;
  int m0 = blockIdx.x * BM, n0 = blockIdx.y * BN;
  int lr = tid >> 2;
  int lc = (tid & 3) << 2;
  float acc[4][4] = {};
  const float* Aptr = A + (size_t)(m0 + lr) * DOUT + lc;
  const float* Bptr = B + (size_t)(n0 + lr) * DOUT + lc;
  bool am = (m0 + lr) < 140;
  bool bn = (n0 + lr) < 140;
  for (int k0 = 0; k0 < KSEG; k0 += BK) {
    float4 av = am ? *(const float4*)(Aptr + k0) : make_float4(0, 0, 0, 0);
    float4 bv = bn ? *(const float4*)(Bptr + k0) : make_float4(0, 0, 0, 0);
    As[lc + 0][lr] = av.x; As[lc + 1][lr] = av.y;
    As[lc + 2][lr] = av.z; As[lc + 3][lr] = av.w;
    Bs[lc + 0][lr] = bv.x; Bs[lc + 1][lr] = bv.y;
    Bs[lc + 2][lr] = bv.z; Bs[lc + 3][lr] = bv.w;
    __syncthreads();
    #pragma unroll
    for (int k = 0; k < BK; k++) {
      float4 a4 = *(const float4*)&As[k][ty << 2];
      float4 b4 = *(const float4*)&Bs[k][tx << 2];
      float ar[4] = {a4.x, a4.y, a4.z, a4.w};
      float br[4] = {b4.x, b4.y, b4.z, b4.w};
      #pragma unroll
      for (int i = 0; i < 4; i++)
        #pragma unroll
        for (int j = 0; j < 4; j++)
          acc[i][j] += ar[i] * br[j];
    }
    __syncthreads();
  }
  #pragma unroll
  for (int i = 0; i < 4; i++) {
    int m = m0 + (ty << 2) + i;
    if (m >= 140) continue;
    #pragma unroll
    for (int j = 0; j < 4; j++) {
      int n = n0 + (tx << 2) + j;
      if (n < 140) C[(size_t)m * 140 + n] = acc[i][j];
    }
  }
}
__global__ void gram_reduce() {
  int i = (blockIdx.x * 256 + threadIdx.x) * 4;
  if (i >= WAY * 19600) return;
  int cls = i / 19600, off = i % 19600;
  const float* base = d_Gp + (size_t)cls * 4 * 19600 + off;
  float4 s0 = *(const float4*)(base);
  float4 s1 = *(const float4*)(base + 19600);
  float4 s2 = *(const float4*)(base + 2 * 19600);
  float4 s3 = *(const float4*)(base + 3 * 19600);
  float4 r;
  r.x = (s0.x + s1.x) + (s2.x + s3.x);
  r.y = (s0.y + s1.y) + (s2.y + s3.y);
  r.z = (s0.z + s1.z) + (s2.z + s3.z);
  r.w = (s0.w + s1.w) + (s2.w + s3.w);
  *(float4*)&d_G[i] = r;
}

// ---------------- kernel: per-item combine (two-pass, 512 threads) -----------
// One block per clip, 16 warps; warp w owns tuples w and w+16.
#define CSMEM (8*NTP*2)
__global__ void __launch_bounds__(512, 2)
combine2(const float* __restrict__ kb, const float* __restrict__ vb,
         const float* __restrict__ gamma, const float* __restrict__ beta) {
  extern __shared__ __half sPh[];   // 8 * 4608 halves
  const int item = blockIdx.x;
  const bool isQ = item < NQv;
  const int tid = threadIdx.x;
  const int lane = tid & 31;
  const int w = tid >> 5;
  const __half* src = d_P + (size_t)item * SEQ * NTP;
  for (int i = tid * 8; i < SEQ * NTP; i += 512 * 8)
    *(uint4*)&sPh[i] = *(const uint4*)&src[i];
  __syncthreads();
  const int mBase = isQ ? item * TLEN : (item - NQv) * TLEN;
  for (int t = w; t < TLEN; t += 16) {
    const int fi = c_tup[2 * t], fj = c_tup[2 * t + 1];
    const __half* pA = sPh + fi * NTP;
    const __half* pB = sPh + fj * NTP;
    const size_t mOff = (size_t)(mBase + t) * DOUT;
    // ---- pass A: LN stats for K + V outputs + ||v||^2 (no x storage) ----
    float s1 = 0.f, s2 = 0.f, qacc = 0.f;
    #pragma unroll 4
    for (int i = 0; i < 36; i++) {
      int d = lane + i * 32;
      float x = __half2float(pA[d]) + __half2float(pB[DOUT + d]) + kb[d];
      s1 += x; s2 += x * x;
      float y = __half2float(pA[2 * DOUT + d]) + __half2float(pB[3 * DOUT + d]) + vb[d];
      if (isQ) { d_QV[mOff + d] = __float2half(y); }
      else     { d_SV[mOff + d] = __float2half(y); d_SVf[mOff + d] = y; }
      qacc += y * y;
    }
    s1 = warpReduceSum(s1);
    s2 = warpReduceSum(s2);
    if (isQ) {
      qacc = warpReduceSum(qacc);
      if (lane == 0) d_qn[mBase + t] = qacc;
    }
    float mu  = s1 * (1.0f / DOUT);
    float var = s2 * (1.0f / DOUT) - mu * mu;
    float inv = rsqrtf(var + 1e-5f);
    // ---- pass B: recompute x from smem, apply LN, write K ----
    #pragma unroll 4
    for (int i = 0; i < 36; i++) {
      int d = lane + i * 32;
      float x = __half2float(pA[d]) + __half2float(pB[DOUT + d]) + kb[d];
      float z = (x - mu) * inv * gamma[d] + beta[d];
      if (isQ) d_QK[mOff + d] = __float2half(z);
      else     d_SK[mOff + d] = __float2half(z);
    }
  }
}

// ---------------- finalize: softmax + Gram quadratic form + logits -----------
// QPB=2 keeps FSMEM at 110KB -> 2 CTAs/SM (the R13 QPB=4 regression lesson).
#define QPB 2
#define FSMEM ((19600 + QPB*TLEN*140 + 8) * 4)
__global__ void __launch_bounds__(256)
finalize_k(const float* __restrict__ gt, const float* __restrict__ tw,
           float* __restrict__ out) {
  extern __shared__ float sm[];
  float* Gs  = sm;                  // 19600
  float* es  = sm + 19600;          // QPB * 28 * 140
  float* red = es + QPB * TLEN * 140;  // 8
  const int qb = blockIdx.x, c = blockIdx.y;
  const int tid = threadIdx.x;
  const int lane = tid & 31;
  const int w = tid >> 5;
  const float* Gsrc = d_G + (size_t)c * 19600;
  for (int idx = tid * 4; idx < 19600; idx += 256 * 4)
    *(float4*)&Gs[idx] = *(const float4*)&Gsrc[idx];
  __syncthreads();

  const float gscale = gt[0] * tw[0];
  #pragma unroll
  for (int qi = 0; qi < QPB; qi++) {
    const int qq = qb * QPB + qi;
    float* e_q = es + qi * TLEN * 140;
    float dist = 0.f;
    if (w < 7) {
      const float scale = rsqrtf((float)DOUT);
      const int t0 = w * 4;
      float Zs[4], TWs[4];
      #pragma unroll
      for (int tt = 0; tt < 4; tt++) {
        const int m = qq * TLEN + t0 + tt;
        const float* Srow = d_S  + (size_t)m * MSP + c * 140;
        const float* Wrow = d_Wm + (size_t)m * MSP + c * 140;
        float ev[5];
        float lmax = -INFINITY;
        #pragma unroll
        for (int i = 0; i < 5; i++) {
          int j = lane + i * 32;
          if (j < 140) { ev[i] = Srow[j] * scale; lmax = fmaxf(lmax, ev[i]); }
          else ev[i] = -INFINITY;
        }
        lmax = warpReduceMax(lmax);
        float lsum = 0.f, lw = 0.f;
        #pragma unroll
        for (int i = 0; i < 5; i++) {
          int j = lane + i * 32;
          if (j < 140) {
            float e = __expf(ev[i] - lmax);
            e_q[(t0 + tt) * 140 + j] = e;
            lsum += e;
            lw   += e * Wrow[j];
          }
        }
        Zs[tt]  = warpReduceSum(lsum);
        TWs[tt] = warpReduceSum(lw);
      }
      __syncwarp();
      float hq[5][4];
      #pragma unroll
      for (int i = 0; i < 5; i++)
        #pragma unroll
        for (int tt = 0; tt < 4; tt++) hq[i][tt] = 0.f;
      for (int j = 0; j < 140; j++) {
        float e4[4];
        #pragma unroll
        for (int tt = 0; tt < 4; tt++) e4[tt] = e_q[(t0 + tt) * 140 + j];
        const float* Grow = Gs + j * 140;
        #pragma unroll
        for (int i = 0; i < 5; i++) {
          int jc = lane + i * 32;
          float g = (jc < 140) ? Grow[jc] : 0.f;
          #pragma unroll
          for (int tt = 0; tt < 4; tt++) hq[i][tt] += g * e4[tt];
        }
      }
      #pragma unroll
      for (int tt = 0; tt < 4; tt++) {
        float qp = 0.f;
        #pragma unroll
        for (int i = 0; i < 5; i++) {
          int jc = lane + i * 32;
          if (jc < 140) qp += hq[i][tt] * e_q[(t0 + tt) * 140 + jc];
        }
        qp = warpReduceSum(qp);
        float invZ = 1.0f / Zs[tt];
        dist += d_qn[qq * TLEN + t0 + tt] - 2.f * TWs[tt] * invZ + qp * invZ * invZ;
      }
    }
    if (lane == 0) red[w] = dist;
    __syncthreads();
    if (tid == 0) {
      float s = 0.f;
      #pragma unroll
      for (int i = 0; i < 7; i++) s += red[i];
      out[qq * WAY + c] = -(s * (1.0f / TLEN)) * gscale;
    }
    __syncthreads();     // red reuse guard for next query
  }
}

// ---------------- launcher ---------------------------------------------------
extern "C" void kernel_launch(void* const* d_in, const int* in_sizes, int n_in,
                              void* d_out, int out_size) {
  const float* support = (const float*)d_in[0];
  /* d_in[1] = support_labels: sorted & balanced; reference uses a reshape */
  const float* queries = (const float*)d_in[2];
  const float* kw    = (const float*)d_in[3];
  const float* kb    = (const float*)d_in[4];
  const float* vw    = (const float*)d_in[5];
  const float* vb    = (const float*)d_in[6];
  const float* gamma = (const float*)d_in[7];
  const float* beta  = (const float*)d_in[8];
  const float* gt    = (const float*)d_in[9];
  const float* tw    = (const float*)d_in[10];
  float* out = (float*)d_out;

  __half *X, *Wt, *P, *QK, *QV, *SK, *SV;
  float *SVf, *S, *Wm;
  cudaGetSymbolAddress((void**)&X,   d_X);
  cudaGetSymbolAddress((void**)&Wt,  d_Wt);
  cudaGetSymbolAddress((void**)&P,   d_P);
  cudaGetSymbolAddress((void**)&QK,  d_QK);
  cudaGetSymbolAddress((void**)&QV,  d_QV);
  cudaGetSymbolAddress((void**)&SK,  d_SK);
  cudaGetSymbolAddress((void**)&SV,  d_SV);
  cudaGetSymbolAddress((void**)&SVf, d_SVf);
  cudaGetSymbolAddress((void**)&S,   d_S);
  cudaGetSymbolAddress((void**)&Wm,  d_Wm);

  cudaFuncSetAttribute(gemm_f16,    cudaFuncAttributeMaxDynamicSharedMemorySize, GSMEM);
  cudaFuncSetAttribute(gemm_scores, cudaFuncAttributeMaxDynamicSharedMemorySize, GSMEM);
  cudaFuncSetAttribute(combine2,    cudaFuncAttributeMaxDynamicSharedMemorySize, CSMEM);
  cudaFuncSetAttribute(finalize_k,  cudaFuncAttributeMaxDynamicSharedMemorySize, FSMEM);

  // launch 0: fused PE table + weight transpose
  pre_w<<<dim3(FEAT / 32, DOUT / 32, 5), dim3(32, 8)>>>(kw, vw);
  // launch 1: frames + PE -> fp16 (vectorized x8)
  prep<<<(MTP * FEAT / 8 + 255) / 256, 256>>>(queries, support);
  // launch 2: all 4 projection planes, fp16 output
  gemm_f16<<<dim3(MTP / 128, NTP / 128), 256, GSMEM>>>(X, Wt, P, FEAT, NTP);
  // launch 3 (ncu-captured): per-item tuple combine + LN, 512 threads
  combine2<<<NQv + NSv, 512, CSMEM>>>(kb, vb, gamma, beta);
  // per-class value Gram partials (K-split x4) + reduce
  gram_part<<<dim3(3, 3, 20), 256>>>(SVf);
  gram_reduce<<<(WAY * 19600 / 4 + 255) / 256, 256>>>();
  // persistent merged scores + value-overlap GEMMs
  gemm_scores<<<296, 256, GSMEM>>>(QK, SK, S, QV, SV, Wm, DOUT, MSP);
  // softmax + quadratic-form distance + logits (2 queries per block)
  finalize_k<<<dim3(NQv / QPB, WAY), 256, FSMEM>>>(gt, tw, out);
}

// round 17
// speedup vs baseline: 1.2972x; 1.0572x over previous
#include <cuda_runtime.h>
#include <cuda_fp16.h>
#include <cstdint>
#include <math.h>

#define SEQ   8
#define FEAT  2048
#define DOUT  1152
#define TLEN  28
#define WAY   5
#define SHOT  5
#define NQv   500
#define NSv   25
#define RQ    (NQv*SEQ)     /* 4000 query frame rows   */
#define RS    (NSv*SEQ)     /* 200 support frame rows  */
#define RALL  (RQ+RS)       /* 4200                    */
#define MQ    (NQv*TLEN)    /* 14000 query tuples      */
#define MS    (NSv*TLEN)    /* 700 support tuples      */

// padded dims (multiples of 128 for the tensor GEMM; no bounds checks needed)
#define MTP   4224          /* padded frame rows                  */
#define NTP   4608          /* 4 planes x 1152 output cols        */
#define MQP   14080         /* padded query tuples                */
#define MSP   768           /* padded support tuples              */

// ---------------- scratch (static device memory; no allocations) -------------
__device__ float   d_PE [SEQ*FEAT];          // positional encoding table
__device__ __half  d_X  [MTP*FEAT];
__device__ __half  d_Wt [NTP*FEAT];
__device__ __half  d_P  [(size_t)MTP*NTP];   // 4-plane frame projections (fp16)
__device__ __half  d_QK [(size_t)MQP*DOUT];
__device__ __half  d_QV [(size_t)MQP*DOUT];
__device__ __half  d_SK [(size_t)MSP*DOUT];
__device__ __half  d_SV [(size_t)MSP*DOUT];
__device__ float   d_SVf[(size_t)MSP*DOUT];
__device__ float   d_S  [(size_t)MQP*MSP];
__device__ float   d_Wm [(size_t)MQP*MSP];
__device__ float   d_qn [MQ];
__device__ float   d_Gp [20*140*140];        // per-(class,kseg) Gram partials
__device__ float   d_G  [WAY*140*140];

__constant__ int c_tup[TLEN*2] = {
  0,1, 0,2, 0,3, 0,4, 0,5, 0,6, 0,7,
  1,2, 1,3, 1,4, 1,5, 1,6, 1,7,
  2,3, 2,4, 2,5, 2,6, 2,7,
  3,4, 3,5, 3,6, 3,7,
  4,5, 4,6, 4,7,
  5,6, 5,7,
  6,7
};

// ======================= generic-target helpers ==============================
__device__ __forceinline__ uint32_t smem_u32(const void* p) {
  uint32_t a;
  asm("{ .reg .u64 t; cvta.to.shared.u64 t, %1; cvt.u32.u64 %0, t; }" : "=r"(a) : "l"(p));
  return a;
}
__device__ __forceinline__ void ldsm4(uint32_t& r0, uint32_t& r1, uint32_t& r2,
                                      uint32_t& r3, uint32_t a) {
  asm volatile("ldmatrix.sync.aligned.m8n8.x4.shared.b16 {%0,%1,%2,%3}, [%4];"
               : "=r"(r0), "=r"(r1), "=r"(r2), "=r"(r3) : "r"(a));
}
__device__ __forceinline__ void mma_f16(float* c, const uint32_t* a, const uint32_t* b) {
  asm volatile("mma.sync.aligned.m16n8k16.row.col.f32.f16.f16.f32 "
               "{%0,%1,%2,%3}, {%4,%5,%6,%7}, {%8,%9}, {%0,%1,%2,%3};"
               : "+f"(c[0]), "+f"(c[1]), "+f"(c[2]), "+f"(c[3])
               : "r"(a[0]), "r"(a[1]), "r"(a[2]), "r"(a[3]), "r"(b[0]), "r"(b[1]));
}
__device__ __forceinline__ float warpReduceSum(float v) {
  #pragma unroll
  for (int o = 16; o; o >>= 1) v += __shfl_xor_sync(0xffffffffu, v, o);
  return v;
}
__device__ __forceinline__ float warpReduceMax(float v) {
  #pragma unroll
  for (int o = 16; o; o >>= 1) v = fmaxf(v, __shfl_xor_sync(0xffffffffu, v, o));
  return v;
}

// ======================= fp16 HMMA GEMM (single product) =====================
#define STAGES  3
#define TILE_B  16384                 /* 128 rows x 64 fp16 (128B rows) */
#define STAGE_B (2*TILE_B)            /* A tile + B tile = 32KB */
#define GSMEM   (STAGES*STAGE_B)      /* 96 KB -> 2 CTAs/SM */

__device__ __forceinline__ void load_stage(
    const __half* __restrict__ A, const __half* __restrict__ B,
    uint32_t stage, int m0, int n0, int k0, int K, int tid)
{
  #pragma unroll
  for (int i = 0; i < 8; i++) {
    int id   = tid + i * 256;
    int tile = id >> 10;                      // 0:A 1:B
    int row  = (id >> 3) & 127;
    int c16  = id & 7;                        // 16B chunk within 128B row
    const __half* base = (tile == 0) ? A : B;
    int r = ((tile == 0) ? m0 : n0) + row;
    const __half* src = base + (size_t)r * K + k0 + c16 * 8;
    uint32_t dst = stage + tile * TILE_B + (row << 7) + ((c16 ^ (row & 7)) << 4);
    asm volatile("cp.async.cg.shared.global [%0], [%1], 16;" :: "r"(dst), "l"(src) : "memory");
  }
  asm volatile("cp.async.commit_group;" ::: "memory");
}

template<int HALF_OUT>
__device__ __forceinline__ void gemm_core(
    const __half* __restrict__ A, const __half* __restrict__ B,
    void* __restrict__ C, int K, int ldc, int m0, int n0, char* smem)
{
  const uint32_t sb = smem_u32(smem);
  const int tid  = threadIdx.x;
  const int lane = tid & 31;
  const int wid  = tid >> 5;
  const int wm   = wid & 1;           // 2 m-blocks of 64
  const int wn   = wid >> 1;          // 4 n-blocks of 32
  const int NC = K >> 6;

  const int q     = lane >> 3;
  const int lrow  = (q & 1) * 8 + (lane & 7);
  const int khalf = q >> 1;

  // smem reuse guard for persistent callers (all warps past previous tile)
  __syncthreads();

  float acc[4][4][4];
  #pragma unroll
  for (int a = 0; a < 4; a++)
    #pragma unroll
    for (int b = 0; b < 4; b++)
      #pragma unroll
      for (int d = 0; d < 4; d++) acc[a][b][d] = 0.f;

  load_stage(A, B, sb + 0 * STAGE_B, m0, n0, 0,  K, tid);
  load_stage(A, B, sb + 1 * STAGE_B, m0, n0, 64, K, tid);

  for (int c = 0; c < NC; c++) {
    asm volatile("cp.async.wait_group 1;" ::: "memory");
    __syncthreads();
    if (c + 2 < NC)
      load_stage(A, B, sb + ((c + 2) % STAGES) * STAGE_B,
                 m0, n0, (c + 2) * 64, K, tid);
    else
      asm volatile("cp.async.commit_group;" ::: "memory");   // keep group count uniform

    const uint32_t st = sb + (c % STAGES) * STAGE_B;
    #pragma unroll
    for (int ks = 0; ks < 4; ks++) {
      const int cc = 2 * ks + khalf;
      uint32_t af[4][4];
      #pragma unroll
      for (int mi = 0; mi < 4; mi++) {
        int r = wm * 64 + mi * 16 + lrow;
        uint32_t ad = st + (r << 7) + ((cc ^ (r & 7)) << 4);
        ldsm4(af[mi][0], af[mi][1], af[mi][2], af[mi][3], ad);
      }
      uint32_t bf[4][2];
      #pragma unroll
      for (int g = 0; g < 2; g++) {
        int r = wn * 32 + g * 16 + lrow;
        uint32_t bd = st + TILE_B + (r << 7) + ((cc ^ (r & 7)) << 4);
        uint32_t t0, t1, t2, t3;
        ldsm4(t0, t1, t2, t3, bd);
        bf[2*g][0] = t0; bf[2*g][1] = t2; bf[2*g+1][0] = t1; bf[2*g+1][1] = t3;
      }
      #pragma unroll
      for (int mi = 0; mi < 4; mi++)
        #pragma unroll
        for (int nj = 0; nj < 4; nj++)
          mma_f16(acc[mi][nj], af[mi], bf[nj]);
    }
  }

  #pragma unroll
  for (int mi = 0; mi < 4; mi++) {
    int r = m0 + wm * 64 + mi * 16 + (lane >> 2);
    #pragma unroll
    for (int nj = 0; nj < 4; nj++) {
      int col = n0 + wn * 32 + nj * 8 + ((lane & 3) << 1);
      if (HALF_OUT) {
        __half* Ch = (__half*)C;
        *(__half2*)&Ch[(size_t)r * ldc + col] =
            __floats2half2_rn(acc[mi][nj][0], acc[mi][nj][1]);
        *(__half2*)&Ch[(size_t)(r + 8) * ldc + col] =
            __floats2half2_rn(acc[mi][nj][2], acc[mi][nj][3]);
      } else {
        float* Cf = (float*)C;
        *(float2*)&Cf[(size_t)r * ldc + col]       = make_float2(acc[mi][nj][0], acc[mi][nj][1]);
        *(float2*)&Cf[(size_t)(r + 8) * ldc + col] = make_float2(acc[mi][nj][2], acc[mi][nj][3]);
      }
    }
  }
}

// projection GEMM: fp16 output
__global__ void __launch_bounds__(256, 2)
gemm_f16(const __half* __restrict__ A, const __half* __restrict__ B,
         __half* __restrict__ C, int K, int ldc)
{
  extern __shared__ char smem[];
  gemm_core<1>(A, B, C, K, ldc, blockIdx.x * 128, blockIdx.y * 128, smem);
}

// persistent merged score GEMMs: tile z=0 -> QK*SK^T -> S ; z=1 -> QV*SV^T -> Wm
#define SC_MT (MQP/128)     /* 110 */
#define SC_NT (MSP/128)     /* 6   */
#define SC_TILES (SC_MT*SC_NT*2)
__global__ void __launch_bounds__(256, 2)
gemm_scores(const __half* __restrict__ QK, const __half* __restrict__ SK,
            float* __restrict__ S,
            const __half* __restrict__ QV, const __half* __restrict__ SV,
            float* __restrict__ Wm, int K, int ldc)
{
  extern __shared__ char smem[];
  for (int tile = blockIdx.x; tile < SC_TILES; tile += gridDim.x) {
    int z  = tile / (SC_MT * SC_NT);
    int t2 = tile % (SC_MT * SC_NT);
    int mi = t2 % SC_MT;                // m-major: concurrent blocks share B panel
    int ni = t2 / SC_MT;
    const __half* A = z ? QV : QK;
    const __half* B = z ? SV : SK;
    float* C        = z ? Wm : S;
    gemm_core<0>(A, B, C, K, ldc, mi * 128, ni * 128, smem);
  }
}

// ---------------- kernel 0: PE table + weight transpose (fused) --------------
// z 0..3 -> transpose plane z ; z==4 -> build PE table
__global__ void pre_w(const float* __restrict__ kw, const float* __restrict__ vw) {
  if (blockIdx.z < 4) {
    __shared__ float tile[32][33];
    int p = blockIdx.z;
    const float* w = (p < 2) ? kw : vw;
    int k0 = blockIdx.x * 32, c0 = blockIdx.y * 32;
    int rbase = (p & 1) * FEAT;
    int tx = threadIdx.x, ty = threadIdx.y;  // 32 x 8
    #pragma unroll
    for (int i = 0; i < 32; i += 8)
      tile[ty + i][tx] = w[(size_t)(rbase + k0 + ty + i) * DOUT + c0 + tx];
    __syncthreads();
    #pragma unroll
    for (int i = 0; i < 32; i += 8) {
      size_t o = (size_t)(p * DOUT + c0 + ty + i) * FEAT + k0 + tx;
      d_Wt[o] = __float2half(tile[tx][ty + i]);
    }
  } else {
    int bid = blockIdx.y * gridDim.x + blockIdx.x;
    int t = bid * 256 + threadIdx.y * 32 + threadIdx.x;
    if (t < SEQ * FEAT) {
      int d  = t & (FEAT - 1);
      int fr = t >> 11;
      float freq = expf((float)(d & ~1) * (-9.210340371976184f / 2048.0f));
      float ang  = (float)fr * freq;
      d_PE[t] = (d & 1) ? cosf(ang) : sinf(ang);
    }
  }
}

// ---------------- kernel 1: frames + PE -> fp16, vectorized x8 ---------------
__global__ void prep(const float* __restrict__ q, const float* __restrict__ s) {
  int i8 = (blockIdx.x * 256 + threadIdx.x) * 8;
  if (i8 >= MTP * FEAT) return;
  int r = i8 >> 11;
  __half h[8];
  if (r >= RALL) {
    #pragma unroll
    for (int i = 0; i < 8; i++) h[i] = __float2half(0.f);
  } else {
    const float* src = (r < RQ) ? (q + i8) : (s + (i8 - RQ * FEAT));
    float4 a = *(const float4*)src;
    float4 b = *(const float4*)(src + 4);
    const float* pe = d_PE + (i8 & (SEQ * FEAT - 1));
    float4 p0 = *(const float4*)pe;
    float4 p1 = *(const float4*)(pe + 4);
    h[0] = __float2half(a.x + p0.x); h[1] = __float2half(a.y + p0.y);
    h[2] = __float2half(a.z + p0.z); h[3] = __float2half(a.w + p0.w);
    h[4] = __float2half(b.x + p1.x); h[5] = __float2half(b.y + p1.y);
    h[6] = __float2half(b.z + p1.z); h[7] = __float2half(b.w + p1.w);
  }
  *(uint4*)&d_X[i8] = *(const uint4*)h;
}

// ---------------- Gram: K-split partials (fp32) + reduce ---------------------
#define BM 64
#define BN 64
#define BK 16
#define KSEG 288
__global__ void __launch_bounds__(256)
gram_part(const float* __restrict__ Abase) {
  const int z = blockIdx.z;                // 0..19 = class*4 + kseg
  const int cls = z >> 2, seg = z & 3;
  const float* A = Abase + (size_t)cls * 140 * DOUT + seg * KSEG;
  const float* B = A;
  float* C = d_Gp + (size_t)z * 19600;
  __shared__ __align__(16) float As[BK][BM + 4];
  __shared__ __align__(16) float Bs[BK][BN + 4];
  int tid = threadIdx.x;
  int tx = tid & 15, ty = tid >> 4;
  int m0 = blockIdx.x * BM, n0 = blockIdx.y * BN;
  int lr = tid >> 2;
  int lc = (tid & 3) << 2;
  float acc[4][4] = {};
  const float* Aptr = A + (size_t)(m0 + lr) * DOUT + lc;
  const float* Bptr = B + (size_t)(n0 + lr) * DOUT + lc;
  bool am = (m0 + lr) < 140;
  bool bn = (n0 + lr) < 140;
  for (int k0 = 0; k0 < KSEG; k0 += BK) {
    float4 av = am ? *(const float4*)(Aptr + k0) : make_float4(0, 0, 0, 0);
    float4 bv = bn ? *(const float4*)(Bptr + k0) : make_float4(0, 0, 0, 0);
    As[lc + 0][lr] = av.x; As[lc + 1][lr] = av.y;
    As[lc + 2][lr] = av.z; As[lc + 3][lr] = av.w;
    Bs[lc + 0][lr] = bv.x; Bs[lc + 1][lr] = bv.y;
    Bs[lc + 2][lr] = bv.z; Bs[lc + 3][lr] = bv.w;
    __syncthreads();
    #pragma unroll
    for (int k = 0; k < BK; k++) {
      float4 a4 = *(const float4*)&As[k][ty << 2];
      float4 b4 = *(const float4*)&Bs[k][tx << 2];
      float ar[4] = {a4.x, a4.y, a4.z, a4.w};
      float br[4] = {b4.x, b4.y, b4.z, b4.w};
      #pragma unroll
      for (int i = 0; i < 4; i++)
        #pragma unroll
        for (int j = 0; j < 4; j++)
          acc[i][j] += ar[i] * br[j];
    }
    __syncthreads();
  }
  #pragma unroll
  for (int i = 0; i < 4; i++) {
    int m = m0 + (ty << 2) + i;
    if (m >= 140) continue;
    #pragma unroll
    for (int j = 0; j < 4; j++) {
      int n = n0 + (tx << 2) + j;
      if (n < 140) C[(size_t)m * 140 + n] = acc[i][j];
    }
  }
}
__global__ void gram_reduce() {
  int i = (blockIdx.x * 256 + threadIdx.x) * 4;
  if (i >= WAY * 19600) return;
  int cls = i / 19600, off = i % 19600;
  const float* base = d_Gp + (size_t)cls * 4 * 19600 + off;
  float4 s0 = *(const float4*)(base);
  float4 s1 = *(const float4*)(base + 19600);
  float4 s2 = *(const float4*)(base + 2 * 19600);
  float4 s3 = *(const float4*)(base + 3 * 19600);
  float4 r;
  r.x = (s0.x + s1.x) + (s2.x + s3.x);
  r.y = (s0.y + s1.y) + (s2.y + s3.y);
  r.z = (s0.z + s1.z) + (s2.z + s3.z);
  r.w = (s0.w + s1.w) + (s2.w + s3.w);
  *(float4*)&d_G[i] = r;
}

// ---------------- kernel: per-item combine (two-pass, 512 thr, half2) --------
// One block per clip, 16 warps; warp w owns tuples w and w+16.
// Each lane handles 2 consecutive elements -> half2/float2 LD/ST everywhere.
#define CSMEM (8*NTP*2)
__global__ void __launch_bounds__(512, 2)
combine2(const float* __restrict__ kb, const float* __restrict__ vb,
         const float* __restrict__ gamma, const float* __restrict__ beta) {
  extern __shared__ __half sPh[];   // 8 * 4608 halves
  const int item = blockIdx.x;
  const bool isQ = item < NQv;
  const int tid = threadIdx.x;
  const int lane = tid & 31;
  const int w = tid >> 5;
  const __half* src = d_P + (size_t)item * SEQ * NTP;
  for (int i = tid * 8; i < SEQ * NTP; i += 512 * 8)
    *(uint4*)&sPh[i] = *(const uint4*)&src[i];
  __syncthreads();
  const int mBase = isQ ? item * TLEN : (item - NQv) * TLEN;
  const float2* kb2    = (const float2*)kb;
  const float2* vb2    = (const float2*)vb;
  const float2* gamma2 = (const float2*)gamma;
  const float2* beta2  = (const float2*)beta;
  for (int t = w; t < TLEN; t += 16) {
    const int fi = c_tup[2 * t], fj = c_tup[2 * t + 1];
    const __half2* pA = (const __half2*)(sPh + fi * NTP);
    const __half2* pB = (const __half2*)(sPh + fj * NTP);
    const size_t mOff = (size_t)(mBase + t) * DOUT;
    __half2* qv2 = (__half2*)((isQ ? d_QV : d_SV) + mOff);
    __half2* qk2 = (__half2*)((isQ ? d_QK : d_SK) + mOff);
    float2*  svf2 = (float2*)(d_SVf + mOff);
    // ---- pass A: LN stats for K + V outputs + ||v||^2 (no x storage) ----
    float s1 = 0.f, s2 = 0.f, qacc = 0.f;
    #pragma unroll 6
    for (int i = 0; i < 18; i++) {
      int h2 = lane + i * 32;                 // half2 index (DOUT/2 = 576)
      float2 a = __half22float2(pA[h2]);
      float2 b = __half22float2(pB[576 + h2]);
      float2 kbv = kb2[h2];
      float x0 = a.x + b.x + kbv.x;
      float x1 = a.y + b.y + kbv.y;
      s1 += x0 + x1; s2 += x0 * x0 + x1 * x1;
      float2 va = __half22float2(pA[2 * 576 + h2]);
      float2 vbv = __half22float2(pB[3 * 576 + h2]);
      float2 vbias = vb2[h2];
      float y0 = va.x + vbv.x + vbias.x;
      float y1 = va.y + vbv.y + vbias.y;
      qv2[h2] = __floats2half2_rn(y0, y1);
      if (!isQ) svf2[h2] = make_float2(y0, y1);
      qacc += y0 * y0 + y1 * y1;
    }
    s1 = warpReduceSum(s1);
    s2 = warpReduceSum(s2);
    if (isQ) {
      qacc = warpReduceSum(qacc);
      if (lane == 0) d_qn[mBase + t] = qacc;
    }
    float mu  = s1 * (1.0f / DOUT);
    float var = s2 * (1.0f / DOUT) - mu * mu;
    float inv = rsqrtf(var + 1e-5f);
    // ---- pass B: recompute x from smem, apply LN, write K ----
    #pragma unroll 6
    for (int i = 0; i < 18; i++) {
      int h2 = lane + i * 32;
      float2 a = __half22float2(pA[h2]);
      float2 b = __half22float2(pB[576 + h2]);
      float2 kbv = kb2[h2];
      float2 g = gamma2[h2];
      float2 be = beta2[h2];
      float z0 = (a.x + b.x + kbv.x - mu) * inv * g.x + be.x;
      float z1 = (a.y + b.y + kbv.y - mu) * inv * g.y + be.y;
      qk2[h2] = __floats2half2_rn(z0, z1);
    }
  }
}

// ---------------- finalize: softmax + Gram quadratic form + logits -----------
// QPB=2 (110KB smem -> 2 CTAs/SM). Phase 2 fuses BOTH queries' tuples per
// G-load (hq[5][8]) -> halves Gram smem traffic per FLOP.
#define QPB 2
#define FSMEM ((19600 + QPB*TLEN*140 + 16) * 4)
__global__ void __launch_bounds__(256)
finalize_k(const float* __restrict__ gt, const float* __restrict__ tw,
           float* __restrict__ out) {
  extern __shared__ float sm[];
  float* Gs  = sm;                  // 19600
  float* es  = sm + 19600;          // QPB * 28 * 140
  float* red = es + QPB * TLEN * 140;  // 16
  const int qb = blockIdx.x, c = blockIdx.y;
  const int tid = threadIdx.x;
  const int lane = tid & 31;
  const int w = tid >> 5;
  const float* Gsrc = d_G + (size_t)c * 19600;
  for (int idx = tid * 4; idx < 19600; idx += 256 * 4)
    *(float4*)&Gs[idx] = *(const float4*)&Gsrc[idx];
  __syncthreads();

  const float gscale = gt[0] * tw[0];
  float dist[QPB] = {0.f, 0.f};
  if (w < 7) {
    const float scale = rsqrtf((float)DOUT);
    const int t0 = w * 4;
    float Zs[QPB][4], TWs[QPB][4];
    // ---- phase 1: softmax stats + unnormalized e for both queries ----
    #pragma unroll
    for (int qi = 0; qi < QPB; qi++) {
      const int qq = qb * QPB + qi;
      float* e_q = es + qi * TLEN * 140;
      #pragma unroll
      for (int tt = 0; tt < 4; tt++) {
        const int m = qq * TLEN + t0 + tt;
        const float* Srow = d_S  + (size_t)m * MSP + c * 140;
        const float* Wrow = d_Wm + (size_t)m * MSP + c * 140;
        float ev[5];
        float lmax = -INFINITY;
        #pragma unroll
        for (int i = 0; i < 5; i++) {
          int j = lane + i * 32;
          if (j < 140) { ev[i] = Srow[j] * scale; lmax = fmaxf(lmax, ev[i]); }
          else ev[i] = -INFINITY;
        }
        lmax = warpReduceMax(lmax);
        float lsum = 0.f, lw = 0.f;
        #pragma unroll
        for (int i = 0; i < 5; i++) {
          int j = lane + i * 32;
          if (j < 140) {
            float e = __expf(ev[i] - lmax);
            e_q[(t0 + tt) * 140 + j] = e;
            lsum += e;
            lw   += e * Wrow[j];
          }
        }
        Zs[qi][tt]  = warpReduceSum(lsum);
        TWs[qi][tt] = warpReduceSum(lw);
      }
    }
    __syncwarp();
    // ---- phase 2: quadratic forms, 8 tuples (2 queries x 4) per G-load ----
    float hq[5][8];
    #pragma unroll
    for (int i = 0; i < 5; i++)
      #pragma unroll
      for (int k = 0; k < 8; k++) hq[i][k] = 0.f;
    for (int j = 0; j < 140; j++) {
      float e8[8];
      #pragma unroll
      for (int qi = 0; qi < QPB; qi++)
        #pragma unroll
        for (int tt = 0; tt < 4; tt++)
          e8[qi * 4 + tt] = es[qi * TLEN * 140 + (t0 + tt) * 140 + j];
      const float* Grow = Gs + j * 140;
      #pragma unroll
      for (int i = 0; i < 5; i++) {
        int jc = lane + i * 32;
        float g = (jc < 140) ? Grow[jc] : 0.f;
        #pragma unroll
        for (int k = 0; k < 8; k++) hq[i][k] += g * e8[k];
      }
    }
    #pragma unroll
    for (int qi = 0; qi < QPB; qi++) {
      const int qq = qb * QPB + qi;
      #pragma unroll
      for (int tt = 0; tt < 4; tt++) {
        float qp = 0.f;
        #pragma unroll
        for (int i = 0; i < 5; i++) {
          int jc = lane + i * 32;
          if (jc < 140) qp += hq[i][qi * 4 + tt] * es[qi * TLEN * 140 + (t0 + tt) * 140 + jc];
        }
        qp = warpReduceSum(qp);
        float invZ = 1.0f / Zs[qi][tt];
        dist[qi] += d_qn[qq * TLEN + t0 + tt] - 2.f * TWs[qi][tt] * invZ + qp * invZ * invZ;
      }
    }
  }
  if (lane == 0) { red[w] = dist[0]; red[8 + w] = dist[1]; }
  __syncthreads();
  if (tid < QPB) {
    float s = 0.f;
    #pragma unroll
    for (int i = 0; i < 7; i++) s += red[tid * 8 + i];
    out[(qb * QPB + tid) * WAY + c] = -(s * (1.0f / TLEN)) * gscale;
  }
}

// ---------------- launcher ---------------------------------------------------
extern "C" void kernel_launch(void* const* d_in, const int* in_sizes, int n_in,
                              void* d_out, int out_size) {
  const float* support = (const float*)d_in[0];
  /* d_in[1] = support_labels: sorted & balanced; reference uses a reshape */
  const float* queries = (const float*)d_in[2];
  const float* kw    = (const float*)d_in[3];
  const float* kb    = (const float*)d_in[4];
  const float* vw    = (const float*)d_in[5];
  const float* vb    = (const float*)d_in[6];
  const float* gamma = (const float*)d_in[7];
  const float* beta  = (const float*)d_in[8];
  const float* gt    = (const float*)d_in[9];
  const float* tw    = (const float*)d_in[10];
  float* out = (float*)d_out;

  __half *X, *Wt, *P, *QK, *QV, *SK, *SV;
  float *SVf, *S, *Wm;
  cudaGetSymbolAddress((void**)&X,   d_X);
  cudaGetSymbolAddress((void**)&Wt,  d_Wt);
  cudaGetSymbolAddress((void**)&P,   d_P);
  cudaGetSymbolAddress((void**)&QK,  d_QK);
  cudaGetSymbolAddress((void**)&QV,  d_QV);
  cudaGetSymbolAddress((void**)&SK,  d_SK);
  cudaGetSymbolAddress((void**)&SV,  d_SV);
  cudaGetSymbolAddress((void**)&SVf, d_SVf);
  cudaGetSymbolAddress((void**)&S,   d_S);
  cudaGetSymbolAddress((void**)&Wm,  d_Wm);

  cudaFuncSetAttribute(gemm_f16,    cudaFuncAttributeMaxDynamicSharedMemorySize, GSMEM);
  cudaFuncSetAttribute(gemm_scores, cudaFuncAttributeMaxDynamicSharedMemorySize, GSMEM);
  cudaFuncSetAttribute(combine2,    cudaFuncAttributeMaxDynamicSharedMemorySize, CSMEM);
  cudaFuncSetAttribute(finalize_k,  cudaFuncAttributeMaxDynamicSharedMemorySize, FSMEM);

  // launch 0: fused PE table + weight transpose
  pre_w<<<dim3(FEAT / 32, DOUT / 32, 5), dim3(32, 8)>>>(kw, vw);
  // launch 1: frames + PE -> fp16 (vectorized x8)
  prep<<<(MTP * FEAT / 8 + 255) / 256, 256>>>(queries, support);
  // launch 2: all 4 projection planes, fp16 output
  gemm_f16<<<dim3(MTP / 128, NTP / 128), 256, GSMEM>>>(X, Wt, P, FEAT, NTP);
  // launch 3 (ncu-captured): per-item tuple combine + LN, 512 threads, half2
  combine2<<<NQv + NSv, 512, CSMEM>>>(kb, vb, gamma, beta);
  // per-class value Gram partials (K-split x4) + reduce
  gram_part<<<dim3(3, 3, 20), 256>>>(SVf);
  gram_reduce<<<(WAY * 19600 / 4 + 255) / 256, 256>>>();
  // persistent merged scores + value-overlap GEMMs
  gemm_scores<<<296, 256, GSMEM>>>(QK, SK, S, QV, SV, Wm, DOUT, MSP);
  // softmax + quadratic-form distance + logits (2 queries per block)
  finalize_k<<<dim3(NQv / QPB, WAY), 256, FSMEM>>>(gt, tw, out);
}